// round 5
// baseline (speedup 1.0000x reference)
#include <cuda_runtime.h>

// CapsuleLayer dynamic routing, multi-kernel factored form.
// X[B=128, I=1152, J=128], W[J=128, K=32, D=32], out V[B=128, K=32, D=32]
//
//  K0 : colsum partials over i (it0's uniform-c GEMM1)
//  K1 : y-reduce -> s[k,d] = sum_j y[k,j] W[j,k,d] -> v = squash(s)
//       -> T[k,j] = sum_d v[k,d] W[j,k,d]  (or final: write v to out)
//  K2 : per (batch, i-split of 288): chunked over 32 i:
//         GEMM2  bl[k,i] (+)= sum_j x[i,j] T[k,j]
//         softmax_k -> c ; GEMM1 y_partial[k,j] += sum_i c[i,k] x[i,j]

#define BB 128
#define II 1152
#define JJ 128
#define KK 32
#define DD 32
#define KD 1024
#define NSPLIT 4
#define ILEN 288         // II / NSPLIT
#define CI 32            // i chunk inside K2
#define NCH 9            // ILEN / CI
#define XPF 132          // xs pitch (floats), conflict-free both orientations
#define C2P 68

typedef unsigned long long u64;

#define FMA2(d,a,b,c) asm("fma.rn.f32x2 %0, %1, %2, %3;" : "=l"(d) : "l"(a), "l"(b), "l"(c))
#define ADD2(d,a,b)   asm("add.rn.f32x2 %0, %1, %2;" : "=l"(d) : "l"(a), "l"(b))

__device__ float g_bl[(size_t)BB * KK * II];            // [b][k][i]
__device__ float g_T[(size_t)BB * KK * JJ];             // [b][k][j]
__device__ float g_yp[(size_t)BB * NSPLIT * KK * JJ];   // [b][s][k][j]
__device__ float g_ycol[(size_t)BB * NSPLIT * JJ];      // [b][p][j]

// ===================== K0: colsum partials =====================
__global__ __launch_bounds__(256)
void k0_colsum(const float* __restrict__ X)
{
    __shared__ ulonglong2 sred[256];
    const int b = blockIdx.y, p = blockIdx.x;
    const int t = threadIdx.x, j4 = t & 31, ih = t >> 5;
    const float* xp = X + (size_t)b * (II * JJ) + (size_t)(p * ILEN + ih * 36) * JJ + j4 * 4;
    u64 s0 = 0, s1 = 0;
    #pragma unroll 4
    for (int ii = 0; ii < 36; ++ii) {
        ulonglong2 v = *(const ulonglong2*)(xp + (size_t)ii * JJ);
        ADD2(s0, s0, v.x); ADD2(s1, s1, v.y);
    }
    sred[ih * 32 + j4] = make_ulonglong2(s0, s1);
    __syncthreads();
    if (t < 32) {
        u64 a0 = 0, a1 = 0;
        #pragma unroll
        for (int h = 0; h < 8; ++h) {
            ulonglong2 v = sred[h * 32 + t];
            ADD2(a0, a0, v.x); ADD2(a1, a1, v.y);
        }
        ((ulonglong2*)(g_ycol + (size_t)(b * NSPLIT + p) * JJ))[t] = make_ulonglong2(a0, a1);
    }
}

// ===================== K1: y -> s -> v -> T / out =====================
#define K1_WT 0          // 16 x 1056 = 16896
#define K1_YM 16896      // 4096 (mode0 uses [0,128))
#define K1_SV 20992      // 1024
#define K1_SC 22016      // 32
#define K1_FLOATS 22048
#define K1_SMEM (K1_FLOATS * 4)

__global__ __launch_bounds__(512)
void k1_svt(const float* __restrict__ W, float* __restrict__ out, int mode)
{
    extern __shared__ float sm[];
    float* wt  = sm + K1_WT;
    float* ym  = sm + K1_YM;
    float* sv  = sm + K1_SV;
    float* scl = sm + K1_SC;

    const int b = blockIdx.x, t = threadIdx.x;
    const int lane = t & 31, w = t >> 5;

    if (mode == 0) {
        if (t < JJ) {
            const float* yc = g_ycol + (size_t)b * NSPLIT * JJ;
            float s = yc[t] + yc[JJ + t] + yc[2 * JJ + t] + yc[3 * JJ + t];
            ym[t] = s * (1.0f / 32.0f);
        }
    } else {
        const float* yp = g_yp + (size_t)b * NSPLIT * KK * JJ;
        #pragma unroll
        for (int pp = 0; pp < 8; ++pp) {
            const int e = t + pp * 512;
            ym[e] = yp[e] + yp[4096 + e] + yp[8192 + e] + yp[12288 + e];
        }
    }
    __syncthreads();

    // s[k][d]
    #pragma unroll
    for (int pp = 0; pp < 2; ++pp) {
        const int p = t + pp * 512;
        const int k = p >> 5, d = p & 31;
        const float* Wp = W + k * DD + d;
        const float* yk = ym + (mode ? k * JJ : 0);
        float acc = 0.f;
        #pragma unroll 8
        for (int j = 0; j < JJ; ++j)
            acc = fmaf(yk[j], Wp[(size_t)j * KD], acc);
        sv[p] = acc;
    }
    __syncthreads();
    // squash
    if (t < KK) {
        float ss = 0.f;
        #pragma unroll
        for (int d = 0; d < DD; ++d) { const float q = sv[t * DD + d]; ss += q * q; }
        scl[t] = ss / (1.0f + ss) * rsqrtf(ss + 1e-7f);
    }
    __syncthreads();
    #pragma unroll
    for (int pp = 0; pp < 2; ++pp) {
        const int p = t + pp * 512;
        sv[p] *= scl[p >> 5];
    }
    __syncthreads();

    if (mode == 2) {
        #pragma unroll
        for (int pp = 0; pp < 2; ++pp) {
            const int p = t + pp * 512;
            out[(size_t)b * KK * DD + p] = sv[p];
        }
        return;
    }

    // T[k][j] = sum_d v[k][d] W[j,k,d]  via per-warp smem transpose
    float* Tg = g_T + (size_t)b * KK * JJ;
    float* wtw = wt + w * 1056;
    #pragma unroll
    for (int kk = 0; kk < 2; ++kk) {
        const int k = 2 * w + kk;
        #pragma unroll
        for (int jb = 0; jb < 4; ++jb) {
            #pragma unroll 8
            for (int j2 = 0; j2 < 32; ++j2)
                wtw[lane * 33 + j2] = W[(size_t)(jb * 32 + j2) * KD + k * DD + lane];
            __syncwarp();
            float acc = 0.f;
            #pragma unroll
            for (int d = 0; d < 32; ++d)
                acc = fmaf(wtw[d * 33 + lane], sv[k * DD + d], acc);
            Tg[k * JJ + jb * 32 + lane] = acc;
            __syncwarp();
        }
    }
}

// ===================== K2: streaming GEMM2 -> softmax -> GEMM1 =====================
#define K2_XS  0         // CI*XPF = 4224
#define K2_TM  4224      // 4096
#define K2_C2  8320      // CI*C2P = 2176
#define K2_BLC 10496     // CI*36  = 1152
#define K2_G2P 11648     // 2*KK*CI = 2048
#define K2_FLOATS 13696
#define K2_SMEM (K2_FLOATS * 4)

__global__ __launch_bounds__(256, 3)
void k2_stream(const float* __restrict__ X, int trans)
{
    extern __shared__ float sm[];
    float* xs  = sm + K2_XS;
    float* Tm  = sm + K2_TM;
    float* c2  = sm + K2_C2;
    float* blc = sm + K2_BLC;
    float* g2p = sm + K2_G2P;

    const int b = blockIdx.y, split = blockIdx.x;
    const int t = threadIdx.x, lane = t & 31, w = t >> 5;   // 8 warps
    const int kg2 = w & 3, js2 = w >> 2;                    // GEMM2: 8 k x 32 i x 64 j
    const int ibase0 = split * ILEN;

    const float* __restrict__ xg = X + (size_t)b * (II * JJ);
    float* __restrict__ blg = g_bl + (size_t)b * (KK * II);

    // load T tile once
    #pragma unroll
    for (int ee = 0; ee < 4; ++ee) {
        const int e4 = t + ee * 256;
        ((float4*)Tm)[e4] = ((const float4*)(g_T + (size_t)b * KK * JJ))[e4];
    }

    u64 a1[4][2];
    #pragma unroll
    for (int q = 0; q < 4; ++q) { a1[q][0] = 0; a1[q][1] = 0; }

    for (int ch = 0; ch < NCH; ++ch) {
        const int ibase = ibase0 + ch * CI;
        __syncthreads();                    // xs / c2 free
        // stage 32 x 128 floats
        #pragma unroll
        for (int ee = 0; ee < 4; ++ee) {
            const int e4 = t + ee * 256;
            const int il = e4 >> 5, j4 = e4 & 31;
            *(float4*)(xs + il * XPF + j4 * 4) =
                *(const float4*)(xg + (size_t)(ibase + il) * JJ + j4 * 4);
        }
        __syncthreads();                    // xs (and, first iter, Tm) visible

        // ---- GEMM2: warp = 8 k x 32 i (lane) x 64 j ----
        {
            u64 a2[8];
            #pragma unroll
            for (int q = 0; q < 8; ++q) a2[q] = 0;
            const float* xr = xs + lane * XPF;
            #pragma unroll 4
            for (int st = 0; st < 16; ++st) {
                const int jq = js2 * 16 + st;
                ulonglong2 xv = *(const ulonglong2*)(xr + jq * 4);
                #pragma unroll
                for (int q = 0; q < 8; ++q) {
                    const int k = kg2 * 8 + q;
                    ulonglong2 tq = *(const ulonglong2*)(Tm + k * JJ + jq * 4); // bcast
                    FMA2(a2[q], tq.x, xv.x, a2[q]);
                    FMA2(a2[q], tq.y, xv.y, a2[q]);
                }
            }
            #pragma unroll
            for (int q = 0; q < 8; ++q) {
                float2 f = *(float2*)&a2[q];
                g2p[js2 * 1024 + (kg2 * 8 + q) * CI + lane] = f.x + f.y;
            }
        }
        __syncthreads();

        // ---- combine j-split partials, update blg, stash blc[i][k] ----
        #pragma unroll
        for (int ee = 0; ee < 4; ++ee) {
            const int e = t + ee * 256;     // e = k*32 + iL
            const int k = e >> 5, iL = e & 31;
            float val = g2p[e] + g2p[1024 + e];
            const size_t gi = (size_t)k * II + ibase + iL;
            if (trans) val += blg[gi];
            blg[gi] = val;
            blc[iL * 36 + k] = val;
        }
        __syncthreads();

        // ---- softmax over k (8 threads per i) ----
        {
            const int i = t >> 3, kq = (t & 7) * 4;
            float4 v4 = *(const float4*)(blc + i * 36 + kq);
            float mx = fmaxf(fmaxf(v4.x, v4.y), fmaxf(v4.z, v4.w));
            #pragma unroll
            for (int off = 1; off < 8; off <<= 1)
                mx = fmaxf(mx, __shfl_xor_sync(0xffffffffu, mx, off));
            const float e0 = __expf(v4.x - mx), e1 = __expf(v4.y - mx);
            const float e2 = __expf(v4.z - mx), e3 = __expf(v4.w - mx);
            float ssum = e0 + e1 + e2 + e3;
            #pragma unroll
            for (int off = 1; off < 8; off <<= 1)
                ssum += __shfl_xor_sync(0xffffffffu, ssum, off);
            const float inv = 1.0f / ssum;
            float* cr = c2 + i * C2P + kq * 2;
            *(float4*)(cr)     = make_float4(e0 * inv, e0 * inv, e1 * inv, e1 * inv);
            *(float4*)(cr + 4) = make_float4(e2 * inv, e2 * inv, e3 * inv, e3 * inv);
        }
        __syncthreads();

        // ---- GEMM1 accumulate: warp = 4 k x 32 i x 128 j ----
        #pragma unroll 4
        for (int ii = 0; ii < CI; ++ii) {
            ulonglong2 xv  = *(const ulonglong2*)(xs + ii * XPF + lane * 4);
            ulonglong2 c01 = *(const ulonglong2*)(c2 + ii * C2P + w * 8);     // bcast
            ulonglong2 c23 = *(const ulonglong2*)(c2 + ii * C2P + w * 8 + 4);
            FMA2(a1[0][0], c01.x, xv.x, a1[0][0]);
            FMA2(a1[0][1], c01.x, xv.y, a1[0][1]);
            FMA2(a1[1][0], c01.y, xv.x, a1[1][0]);
            FMA2(a1[1][1], c01.y, xv.y, a1[1][1]);
            FMA2(a1[2][0], c23.x, xv.x, a1[2][0]);
            FMA2(a1[2][1], c23.x, xv.y, a1[2][1]);
            FMA2(a1[3][0], c23.y, xv.x, a1[3][0]);
            FMA2(a1[3][1], c23.y, xv.y, a1[3][1]);
        }
    }

    // write y partials: warp w owns k = 4w..4w+3
    float* yp = g_yp + ((size_t)b * NSPLIT + split) * KK * JJ;
    #pragma unroll
    for (int q = 0; q < 4; ++q)
        *(ulonglong2*)(yp + (w * 4 + q) * JJ + lane * 4) =
            make_ulonglong2(a1[q][0], a1[q][1]);
}

extern "C" void kernel_launch(void* const* d_in, const int* in_sizes, int n_in,
                              void* d_out, int out_size)
{
    (void)in_sizes; (void)n_in; (void)out_size;
    const float* X = (const float*)d_in[0];   // [128, 1152, 128] f32
    const float* W = (const float*)d_in[1];   // [128, 32, 32] f32
    float* out = (float*)d_out;               // [128, 32, 32] f32

    cudaFuncSetAttribute(k1_svt, cudaFuncAttributeMaxDynamicSharedMemorySize, K1_SMEM);
    cudaFuncSetAttribute(k2_stream, cudaFuncAttributeMaxDynamicSharedMemorySize, K2_SMEM);

    k0_colsum<<<dim3(NSPLIT, BB), 256>>>(X);
    k1_svt<<<BB, 512, K1_SMEM>>>(W, out, 0);
    k2_stream<<<dim3(NSPLIT, BB), 256, K2_SMEM>>>(X, 0);
    k1_svt<<<BB, 512, K1_SMEM>>>(W, out, 1);
    k2_stream<<<dim3(NSPLIT, BB), 256, K2_SMEM>>>(X, 1);
    k1_svt<<<BB, 512, K1_SMEM>>>(W, out, 2);
}

// round 6
// speedup vs baseline: 1.3852x; 1.3852x over previous
#include <cuda_runtime.h>

// CapsuleLayer dynamic routing, multi-kernel factored form v2.
// X[B=128, I=1152, J=128], W[J=128, K=32, D=32], out V[B=128, K=32, D=32]
//
//  k_pre: Wkjd[k][j][d] = W[j][k][d] ; Wkdj[k][d][j] = W[j][k][d]
//  k0   : colsum partials over i (it0 uniform-c GEMM1)
//  k1   : per (kq,b): y-reduce -> s -> squash -> T (mode 0/1) or out (mode 2)
//  k2   : per (split,b), 3 chunks of 64 i:
//           GEMM2 bl[k,i] (+)= sum_j x[i,j] T[k,j]  (full bl per warp, no partials)
//           in-place softmax_k ; GEMM1 y_partial[k,j] += sum_i c[i,k] x[i,j]

#define BB 128
#define II 1152
#define JJ 128
#define KK 32
#define DD 32
#define KD 1024
#define NSPLIT 6
#define ILEN 192         // II / NSPLIT
#define CI 64
#define NCH 3            // ILEN / CI
#define XPF 132
#define NYP (NSPLIT*2)   // 12 y-partial slots (i-half per CTA)

typedef unsigned long long u64;

#define FMA2(d,a,b,c) asm("fma.rn.f32x2 %0, %1, %2, %3;" : "=l"(d) : "l"(a), "l"(b), "l"(c))
#define ADD2(d,a,b)   asm("add.rn.f32x2 %0, %1, %2;" : "=l"(d) : "l"(a), "l"(b))
#define PACK2(d,s)    asm("mov.b64 %0, {%1, %1};" : "=l"(d) : "r"(__float_as_uint(s)))

__device__ float g_bl[(size_t)BB * KK * II];          // [b][k][i]
__device__ float g_T[(size_t)BB * KK * JJ];           // [b][k][j]
__device__ float g_yp[(size_t)BB * NYP * KK * JJ];    // [b][slot][k][j]
__device__ float g_ycol[(size_t)BB * 4 * JJ];         // [b][p][j]
__device__ float g_Wkjd[(size_t)KK * JJ * DD];        // [k][j][d]
__device__ float g_Wkdj[(size_t)KK * DD * JJ];        // [k][d][j]

// ===================== k_pre: W transposes =====================
__global__ __launch_bounds__(256)
void k_pre(const float* __restrict__ W)
{
    __shared__ float tile[JJ * 33];
    const int k = blockIdx.x, t = threadIdx.x;
    // load W[j][k][d] for this k: thread (j, d)
    #pragma unroll
    for (int ee = 0; ee < 16; ++ee) {
        const int idx = t + ee * 256;          // 4096
        const int j = idx >> 5, d = idx & 31;
        const float v = W[(size_t)j * KD + k * DD + d];   // coalesced over d
        tile[j * 33 + d] = v;
        g_Wkjd[(size_t)k * 4096 + j * 32 + d] = v;        // coalesced
    }
    __syncthreads();
    #pragma unroll
    for (int ee = 0; ee < 16; ++ee) {
        const int idx = t + ee * 256;
        const int d = idx >> 7, j = idx & 127;
        g_Wkdj[(size_t)k * 4096 + d * 128 + j] = tile[j * 33 + d];  // coalesced
    }
}

// ===================== k0: colsum partials =====================
__global__ __launch_bounds__(256)
void k0_colsum(const float* __restrict__ X)
{
    __shared__ ulonglong2 sred[256];
    const int b = blockIdx.y, p = blockIdx.x;
    const int t = threadIdx.x, j4 = t & 31, ih = t >> 5;
    const float* xp = X + (size_t)b * (II * JJ) + (size_t)(p * 288 + ih * 36) * JJ + j4 * 4;
    u64 s0 = 0, s1 = 0;
    #pragma unroll 4
    for (int ii = 0; ii < 36; ++ii) {
        ulonglong2 v = *(const ulonglong2*)(xp + (size_t)ii * JJ);
        ADD2(s0, s0, v.x); ADD2(s1, s1, v.y);
    }
    sred[ih * 32 + j4] = make_ulonglong2(s0, s1);
    __syncthreads();
    if (t < 32) {
        u64 a0 = 0, a1 = 0;
        #pragma unroll
        for (int h = 0; h < 8; ++h) {
            ulonglong2 v = sred[h * 32 + t];
            ADD2(a0, a0, v.x); ADD2(a1, a1, v.y);
        }
        ((ulonglong2*)(g_ycol + (size_t)(b * 4 + p) * JJ))[t] = make_ulonglong2(a0, a1);
    }
}

// ===================== k1: y -> s -> v -> T / out =====================
__global__ __launch_bounds__(256)
void k1_svt(float* __restrict__ out, int mode)
{
    __shared__ float ym[8 * JJ];
    __shared__ float sv[8 * DD];

    const int b = blockIdx.y, kq = blockIdx.x;
    const int t = threadIdx.x, lane = t & 31, kl = t >> 5;   // 8 warps, warp=one k
    const int k = kq * 8 + kl;

    if (mode == 0) {
        const float* yc = g_ycol + (size_t)b * 4 * JJ;
        #pragma unroll
        for (int pp = 0; pp < 4; ++pp) {
            const int idx = t + pp * 256;                    // 1024
            const int j = idx & 127;
            ym[idx] = (yc[j] + yc[128 + j] + yc[256 + j] + yc[384 + j]) * (1.0f / 32.0f);
        }
    } else {
        const float* yp = g_yp + (size_t)b * NYP * KK * JJ;
        #pragma unroll
        for (int pp = 0; pp < 4; ++pp) {
            const int idx = t + pp * 256;
            const int kl2 = idx >> 7, j = idx & 127;
            const size_t off = (size_t)(kq * 8 + kl2) * JJ + j;
            float acc = 0.f;
            #pragma unroll
            for (int s = 0; s < NYP; ++s)
                acc += yp[(size_t)s * KK * JJ + off];
            ym[idx] = acc;
        }
    }
    __syncthreads();

    // s[k][d]: thread (kl, d=lane), coalesced Wkjd rows
    float sacc = 0.f;
    {
        const float* Wp = g_Wkjd + (size_t)k * 4096 + lane;
        const float* yk = ym + kl * JJ;
        #pragma unroll 16
        for (int j = 0; j < JJ; ++j)
            sacc = fmaf(yk[j], Wp[j * 32], sacc);
    }
    // squash via warp reduce
    float ss = sacc * sacc;
    #pragma unroll
    for (int off = 16; off > 0; off >>= 1)
        ss += __shfl_xor_sync(0xffffffffu, ss, off);
    const float scale = ss / (1.0f + ss) * rsqrtf(ss + 1e-7f);
    const float v = sacc * scale;

    if (mode == 2) {
        out[(size_t)b * KK * DD + k * DD + lane] = v;
        return;
    }

    sv[kl * DD + lane] = v;
    __syncwarp();

    // T[k][j]: warp kl, j = lane + 32q, coalesced Wkdj rows
    float* Tg = g_T + (size_t)b * KK * JJ + k * JJ;
    float ta[4] = {0.f, 0.f, 0.f, 0.f};
    const float* Wd = g_Wkdj + (size_t)k * 4096 + lane;
    #pragma unroll 8
    for (int d = 0; d < DD; ++d) {
        const float vd = sv[kl * DD + d];
        const float* r = Wd + d * 128;
        #pragma unroll
        for (int q = 0; q < 4; ++q)
            ta[q] = fmaf(vd, r[32 * q], ta[q]);
    }
    #pragma unroll
    for (int q = 0; q < 4; ++q)
        Tg[lane + 32 * q] = ta[q];
}

// ===================== k2: streaming GEMM2 -> softmax -> GEMM1 =====================
#define K2_XS 0          // 64*132 = 8448
#define K2_TM 8448       // 4096
#define K2_BL 12544      // 64*36 = 2304  (bl chunk, softmax in place)
#define K2_FLOATS 14848
#define K2_SMEM (K2_FLOATS * 4)

__global__ __launch_bounds__(256, 3)
void k2_stream(const float* __restrict__ X, int trans)
{
    extern __shared__ float sm[];
    float* xs  = sm + K2_XS;
    float* Tm  = sm + K2_TM;
    float* blc = sm + K2_BL;

    const int b = blockIdx.y, split = blockIdx.x;
    const int t = threadIdx.x, lane = t & 31, w = t >> 5;   // 8 warps
    const int kg = w & 3, ih = w >> 2;                      // 8 k's, i-half
    const int ibase0 = split * ILEN;

    const float* __restrict__ xg = X + (size_t)b * (II * JJ);
    float* __restrict__ blg = g_bl + (size_t)b * (KK * II);

    // load T tile (4096 f)
    {
        const float4* Tg = (const float4*)(g_T + (size_t)b * KK * JJ);
        #pragma unroll
        for (int ee = 0; ee < 4; ++ee)
            ((float4*)Tm)[t + ee * 256] = Tg[t + ee * 256];
    }

    u64 a1[8][2];
    #pragma unroll
    for (int q = 0; q < 8; ++q) { a1[q][0] = 0; a1[q][1] = 0; }

    for (int ch = 0; ch < NCH; ++ch) {
        const int ibase = ibase0 + ch * CI;
        __syncthreads();                      // xs free (also orders Tm on ch0)
        // stage 64x128 f (8 float4 per thread, coalesced)
        #pragma unroll
        for (int ee = 0; ee < 8; ++ee) {
            const int e4 = t + ee * 256;
            const int il = e4 >> 5, j4 = e4 & 31;
            *(float4*)(xs + il * XPF + j4 * 4) =
                *(const float4*)(xg + (size_t)(ibase + il) * JJ + j4 * 4);
        }
        // prefetch old bl for += (independent of smem)
        float blold[8];
        if (trans) {
            #pragma unroll
            for (int q = 0; q < 8; ++q)
                blold[q] = blg[(size_t)(kg * 8 + q) * II + ibase + ih * 32 + lane];
        }
        __syncthreads();

        // ---- GEMM2: warp = 8 k x 32 i (lane, half ih) x full 128 j ----
        {
            u64 a2[8];
            #pragma unroll
            for (int q = 0; q < 8; ++q) a2[q] = 0;
            const float* xr = xs + (ih * 32 + lane) * XPF;
            #pragma unroll 4
            for (int jq = 0; jq < 32; ++jq) {
                ulonglong2 xv = *(const ulonglong2*)(xr + jq * 4);
                #pragma unroll
                for (int q = 0; q < 8; ++q) {
                    ulonglong2 tq = *(const ulonglong2*)(Tm + (kg * 8 + q) * JJ + jq * 4);
                    FMA2(a2[q], tq.x, xv.x, a2[q]);
                    FMA2(a2[q], tq.y, xv.y, a2[q]);
                }
            }
            #pragma unroll
            for (int q = 0; q < 8; ++q) {
                float2 f = *(float2*)&a2[q];
                float val = f.x + f.y;
                if (trans) val += blold[q];
                blg[(size_t)(kg * 8 + q) * II + ibase + ih * 32 + lane] = val;
                blc[(ih * 32 + lane) * 36 + kg * 8 + q] = val;
            }
        }
        __syncthreads();

        // ---- softmax over k, in place (4 threads per i, 8 k each) ----
        {
            const int i = t >> 2, kq8 = (t & 3) * 8;
            float* r = blc + i * 36 + kq8;
            float4 u0 = *(const float4*)(r);
            float4 u1 = *(const float4*)(r + 4);
            float mx = fmaxf(fmaxf(fmaxf(u0.x, u0.y), fmaxf(u0.z, u0.w)),
                             fmaxf(fmaxf(u1.x, u1.y), fmaxf(u1.z, u1.w)));
            mx = fmaxf(mx, __shfl_xor_sync(0xffffffffu, mx, 1));
            mx = fmaxf(mx, __shfl_xor_sync(0xffffffffu, mx, 2));
            u0.x = __expf(u0.x - mx); u0.y = __expf(u0.y - mx);
            u0.z = __expf(u0.z - mx); u0.w = __expf(u0.w - mx);
            u1.x = __expf(u1.x - mx); u1.y = __expf(u1.y - mx);
            u1.z = __expf(u1.z - mx); u1.w = __expf(u1.w - mx);
            float ssum = u0.x + u0.y + u0.z + u0.w + u1.x + u1.y + u1.z + u1.w;
            ssum += __shfl_xor_sync(0xffffffffu, ssum, 1);
            ssum += __shfl_xor_sync(0xffffffffu, ssum, 2);
            const float inv = 1.0f / ssum;
            u0.x *= inv; u0.y *= inv; u0.z *= inv; u0.w *= inv;
            u1.x *= inv; u1.y *= inv; u1.z *= inv; u1.w *= inv;
            *(float4*)(r) = u0;
            *(float4*)(r + 4) = u1;
        }
        __syncthreads();

        // ---- GEMM1: warp = 8 k x 32 i (half ih) x full 128 j (lane*4) ----
        #pragma unroll 2
        for (int ii = 0; ii < 32; ++ii) {
            const int i = ih * 32 + ii;
            ulonglong2 xv = *(const ulonglong2*)(xs + i * XPF + lane * 4);
            const float* cr = blc + i * 36 + kg * 8;         // broadcast
            float4 c0 = *(const float4*)(cr);
            float4 c1 = *(const float4*)(cr + 4);
            u64 cc;
            PACK2(cc, c0.x); FMA2(a1[0][0], cc, xv.x, a1[0][0]); FMA2(a1[0][1], cc, xv.y, a1[0][1]);
            PACK2(cc, c0.y); FMA2(a1[1][0], cc, xv.x, a1[1][0]); FMA2(a1[1][1], cc, xv.y, a1[1][1]);
            PACK2(cc, c0.z); FMA2(a1[2][0], cc, xv.x, a1[2][0]); FMA2(a1[2][1], cc, xv.y, a1[2][1]);
            PACK2(cc, c0.w); FMA2(a1[3][0], cc, xv.x, a1[3][0]); FMA2(a1[3][1], cc, xv.y, a1[3][1]);
            PACK2(cc, c1.x); FMA2(a1[4][0], cc, xv.x, a1[4][0]); FMA2(a1[4][1], cc, xv.y, a1[4][1]);
            PACK2(cc, c1.y); FMA2(a1[5][0], cc, xv.x, a1[5][0]); FMA2(a1[5][1], cc, xv.y, a1[5][1]);
            PACK2(cc, c1.z); FMA2(a1[6][0], cc, xv.x, a1[6][0]); FMA2(a1[6][1], cc, xv.y, a1[6][1]);
            PACK2(cc, c1.w); FMA2(a1[7][0], cc, xv.x, a1[7][0]); FMA2(a1[7][1], cc, xv.y, a1[7][1]);
        }
    }

    // y partial slot = (split, ih): warp kg owns k = kg*8..kg*8+7
    float* yp = g_yp + ((size_t)(b * NSPLIT + split) * 2 + ih) * KK * JJ;
    #pragma unroll
    for (int q = 0; q < 8; ++q)
        *(ulonglong2*)(yp + (kg * 8 + q) * JJ + lane * 4) =
            make_ulonglong2(a1[q][0], a1[q][1]);
}

extern "C" void kernel_launch(void* const* d_in, const int* in_sizes, int n_in,
                              void* d_out, int out_size)
{
    (void)in_sizes; (void)n_in; (void)out_size;
    const float* X = (const float*)d_in[0];   // [128, 1152, 128] f32
    const float* W = (const float*)d_in[1];   // [128, 32, 32] f32
    float* out = (float*)d_out;               // [128, 32, 32] f32

    cudaFuncSetAttribute(k2_stream, cudaFuncAttributeMaxDynamicSharedMemorySize, K2_SMEM);

    k_pre<<<KK, 256>>>(W);
    k0_colsum<<<dim3(4, BB), 256>>>(X);
    k1_svt<<<dim3(4, BB), 256>>>(out, 0);
    k2_stream<<<dim3(NSPLIT, BB), 256, K2_SMEM>>>(X, 0);
    k1_svt<<<dim3(4, BB), 256>>>(out, 1);
    k2_stream<<<dim3(NSPLIT, BB), 256, K2_SMEM>>>(X, 1);
    k1_svt<<<dim3(4, BB), 256>>>(out, 2);
}